// round 4
// baseline (speedup 1.0000x reference)
#include <cuda_runtime.h>
#include <cstdint>

typedef unsigned long long u64;

#define KOUT 512
#define NT   512
#define CAP  2048
#define TRIG 1024          // compact when cnt > TRIG (tile inserts <= 1024 fit)
#define TILE (2 * NT)      // 1024 points per tile (one float4 per thread)
#define NB   2048
#define BPT  (NB / NT)     // 4

__device__ __forceinline__ unsigned fkey(float f) {
    unsigned u = __float_as_uint(f);
    return u ^ ((u & 0x80000000u) ? 0xFFFFFFFFu : 0x80000000u);
}
__device__ __forceinline__ float finv(unsigned v) {
    unsigned u = v ^ ((v & 0x80000000u) ? 0x80000000u : 0xFFFFFFFFu);
    return __uint_as_float(u);
}
__device__ __forceinline__ u64 pack(float x, float y) {
    return ((u64)fkey(x) << 32) | (u64)fkey(y);
}

struct Sh {
    u64 buf[CAP];
    u64 buf2[CAP];
    int hist[NB];
    int wsum[NT / 32];
    int cnt, cnt2, pivot, below;
    u64 T;
};

// warp-aggregated push of (pred ? key : nothing) into buf/cnt
__device__ __forceinline__ void wa_push(Sh& sh, bool pred, u64 key) {
    unsigned mask = __ballot_sync(0xFFFFFFFFu, pred);
    if (!mask) return;
    int lane = threadIdx.x & 31;
    int leader = __ffs(mask) - 1;
    int base;
    if (lane == leader) base = atomicAdd(&sh.cnt, __popc(mask));
    base = __shfl_sync(0xFFFFFFFFu, base, leader);
    if (pred) {
        int pos = base + __popc(mask & ((1u << lane) - 1));
        if (pos < CAP) sh.buf[pos] = key;
    }
}

// smallest bin p with cumsum >= target; sets sh.pivot / sh.below
__device__ void find_pivot(Sh& sh, int target) {
    const int t = threadIdx.x;
    const int base = t * BPT;
    int local = 0;
#pragma unroll
    for (int j = 0; j < BPT; j++) local += sh.hist[base + j];
    const int lane = t & 31, warp = t >> 5;
    int incl = local;
#pragma unroll
    for (int o = 1; o < 32; o <<= 1) {
        int v = __shfl_up_sync(0xFFFFFFFFu, incl, o);
        if (lane >= o) incl += v;
    }
    if (lane == 31) sh.wsum[warp] = incl;
    __syncthreads();
    if (t == 0) {
        int acc = 0;
#pragma unroll
        for (int i = 0; i < NT / 32; i++) { int v = sh.wsum[i]; sh.wsum[i] = acc; acc += v; }
    }
    __syncthreads();
    const int excl = sh.wsum[warp] + incl - local;
    if (excl < target && excl + local >= target) {
        int c = excl;
#pragma unroll
        for (int j = 0; j < BPT; j++) {
            int h = sh.hist[base + j];
            if (c + h >= target) { sh.pivot = base + j; sh.below = c; break; }
            c += h;
        }
    }
    __syncthreads();
}

__device__ void bitonic(u64* a, int P) {
    const int t = threadIdx.x;
    for (int size = 2; size <= P; size <<= 1) {
        for (int stride = size >> 1; stride > 0; stride >>= 1) {
            for (int i = t; i < P; i += NT) {
                int j = i ^ stride;
                if (j > i) {
                    u64 x = a[i], y = a[j];
                    bool up = ((i & size) == 0);
                    if ((x > y) == up) { a[i] = y; a[j] = x; }
                }
            }
            __syncthreads();
        }
    }
}

// Compact buffer: keep keys < newT (bin-granular), guaranteeing all of the
// kk smallest seen keys stay. Exact-sort fallback if no shrink.
__device__ void compact(Sh& sh, int kk) {
    const int t = threadIdx.x;
    const int cnt = sh.cnt;
    for (int i = t; i < NB; i += NT) sh.hist[i] = 0;
    __syncthreads();
    for (int i = t; i < cnt; i += NT)
        atomicAdd(&sh.hist[(int)(sh.buf[i] >> 53)], 1);
    __syncthreads();
    find_pivot(sh, kk);
    u64 newT = ((u64)(sh.pivot + 1)) << 53;

    if (t == 0) sh.cnt2 = 0;
    __syncthreads();
    for (int i = t; i < cnt; i += NT) {
        u64 k = sh.buf[i];
        if (k < newT) { int pos = atomicAdd(&sh.cnt2, 1); sh.buf2[pos] = k; }
    }
    __syncthreads();
    int c2 = sh.cnt2;

    if (c2 > TRIG) {  // pathological (duplicate-heavy bin): exact selection
        int P = 1; while (P < c2) P <<= 1;
        for (int i = c2 + t; i < P; i += NT) sh.buf2[i] = ~0ull;
        __syncthreads();
        bitonic(sh.buf2, P);
        newT = sh.buf2[KOUT - 1];
        c2 = KOUT;
        __syncthreads();
    }
    for (int i = t; i < c2; i += NT) sh.buf[i] = sh.buf2[i];
    if (t == 0) { sh.cnt = c2; sh.T = newT; }
    __syncthreads();
}

__global__ __launch_bounds__(NT)
void topk_stream_kernel(const float2* __restrict__ corners,
                        const int*    __restrict__ lengths,
                        float2*       __restrict__ out,
                        int M) {
    __shared__ Sh sh;
    const int b = blockIdx.x;
    const int t = threadIdx.x;
    const int n  = lengths[b];
    const int kk = n < KOUT ? n : KOUT;
    float2* outp = out + (size_t)b * KOUT;

    if (kk == 0) { outp[t] = make_float2(0.f, 0.f); return; }

    const float2* base = corners + (size_t)b * M;

    if (t == 0) { sh.cnt = 0; sh.T = ~0ull; }
    __syncthreads();

    // prefetch tile 0
    float4 v; int fl = 0;
    {
        int i = 2 * t;
        if (i + 1 < n) { v = *(const float4*)(base + i); fl = 2; }
        else if (i < n) { float2 c = base[i]; v.x = c.x; v.y = c.y; fl = 1; }
    }

    for (int i0 = 0; i0 < n; i0 += TILE) {
        // prefetch next tile into registers (crosses the barrier: reg-only)
        float4 vn; int fln = 0;
        {
            int i = i0 + TILE + 2 * t;
            if (i + 1 < n) { vn = *(const float4*)(base + i); fln = 2; }
            else if (i < n) { float2 c = base[i]; vn.x = c.x; vn.y = c.y; fln = 1; }
        }
        u64 T = sh.T;
        u64 k0 = pack(v.x, v.y);
        u64 k1 = pack(v.z, v.w);
        wa_push(sh, fl >= 1 && k0 < T, k0);
        wa_push(sh, fl == 2 && k1 < T, k1);
        __syncthreads();
        if (sh.cnt > TRIG) compact(sh, kk);
        v = vn; fl = fln;
    }

    // shrink before final sort if needed (post-compact cnt <= TRIG)
    if (sh.cnt > TRIG) compact(sh, kk);

    int C = sh.cnt;           // kk <= C <= CAP
    int P = 1; while (P < C) P <<= 1;
    if (P < 2) P = 2;
    for (int i = C + t; i < P; i += NT) sh.buf[i] = ~0ull;
    __syncthreads();
    bitonic(sh.buf, P);

    float2 o = make_float2(0.f, 0.f);
    if (t < kk) {
        u64 k = sh.buf[t];
        o = make_float2(finv((unsigned)(k >> 32)), finv((unsigned)k));
    }
    outp[t] = o;
}

extern "C" void kernel_launch(void* const* d_in, const int* in_sizes, int n_in,
                              void* d_out, int out_size) {
    const float2* corners = (const float2*)d_in[0];
    const int*    lengths = (const int*)d_in[1];
    float2*       out     = (float2*)d_out;
    const int B = in_sizes[1];
    const int M = in_sizes[0] / (B * 2);
    topk_stream_kernel<<<B, NT>>>(corners, lengths, out, M);
}